// round 9
// baseline (speedup 1.0000x reference)
#include <cuda_runtime.h>
#include <cuda_fp16.h>
#include <cstdint>

#define NMAX   100352
#define EMAX   3276800
#define C_IN   300
#define C1     64
#define HEADS  4
#define OUT2   32
#define SLOPE  0.2f

// ---------------- device scratch ----------------
__device__ __align__(16) __half g_hh[(size_t)NMAX * C1];    // x@W1 fp16    [N,64]
__device__ __align__(16) float  g_x1[(size_t)NMAX * C1];    // relu(GAT)+b1 [N,64]
__device__ __align__(16) float  g_as[(size_t)NMAX * HEADS];
__device__ __align__(16) float  g_ad[(size_t)NMAX * HEADS];
__device__ __align__(16) float  g_h2[(size_t)NMAX * OUT2];  // x1@W2 fp32   [N,32]
__device__ __align__(16) __half g_h2h[(size_t)NMAX * OUT2]; // fp16 mirror  [N,32]
__device__ __align__(16) float  g_dinv[NMAX];
__device__ int g_dega[NMAX], g_degb[NMAX];
__device__ int g_roffa[NMAX], g_roffb[NMAX];
__device__ int g_cura[NMAX],  g_curb[NMAX];
__device__ int g_csra[EMAX],  g_csrb[EMAX];
__device__ int g_bsa[1024],   g_bsb[1024];
__device__ int g_is64_a, g_is64_b;

__device__ __forceinline__ float leaky(float v) { return v > 0.f ? v : SLOPE * v; }

__device__ __forceinline__ uint64_t pack2(float lo, float hi) {
    uint64_t r; asm("mov.b64 %0,{%1,%2};" : "=l"(r) : "f"(lo), "f"(hi)); return r;
}
__device__ __forceinline__ float2 unpack2(uint64_t v) {
    float2 f; asm("mov.b64 {%0,%1},%2;" : "=f"(f.x), "=f"(f.y) : "l"(v)); return f;
}
__device__ __forceinline__ void ffma2(uint64_t& d, uint64_t a, uint64_t b) {
    asm("fma.rn.f32x2 %0, %1, %2, %0;" : "+l"(d) : "l"(a), "l"(b));
}

__device__ __forceinline__ void load_edge(const int* __restrict__ ei,
                                          long long E, long long e, int is64,
                                          int& src, int& dst) {
    if (is64) {
        src = (int)((const long long*)ei)[e];
        dst = (int)((const long long*)ei)[E + e];
    } else {
        src = ei[(size_t)e];
        dst = ei[(size_t)(E + e)];
    }
}

// ---------------- K0: detect edge dtype ----------------
__global__ void k_detect(const int* __restrict__ a, const int* __restrict__ b) {
    __shared__ int sa, sb;
    if (threadIdx.x == 0) { sa = 0; sb = 0; }
    __syncthreads();
    atomicOr(&sa, a[2 * threadIdx.x + 1]);
    atomicOr(&sb, b[2 * threadIdx.x + 1]);
    __syncthreads();
    if (threadIdx.x == 0) {
        g_is64_a = (sa == 0) ? 1 : 0;
        g_is64_b = (sb == 0) ? 1 : 0;
    }
}
__global__ void k_zero(int* __restrict__ deg, int n) {
    int i = blockIdx.x * blockDim.x + threadIdx.x;
    if (i < n) deg[i] = 0;
}

// ---------------- K1: h = x @ W1 (f32x2) + fused attn reduction ----------
#define KT 64
__global__ void k_gemm1(const float* __restrict__ x,
                        const float* __restrict__ W1,
                        const float* __restrict__ att_src,
                        const float* __restrict__ att_dst, int N) {
    __shared__ float xs[KT][68];
    __shared__ float Ws[KT][64];
    const int tid = threadIdx.x;
    const int nb  = blockIdx.x * 64;
    const int n0  = (tid >> 4) * 4;
    const int c0  = (tid & 15) * 4;

    uint64_t acc[4][2];
#pragma unroll
    for (int i = 0; i < 4; i++) { acc[i][0] = pack2(0.f, 0.f); acc[i][1] = pack2(0.f, 0.f); }

    for (int j0 = 0; j0 < C_IN; j0 += KT) {
#pragma unroll
        for (int k = 0; k < (64 * KT) / 256; k++) {
            int idx = tid + k * 256;
            int n = idx / KT, j = idx % KT;
            int nn = nb + n;
            float v = 0.f;
            if ((j0 + j) < C_IN && nn < N) v = x[(size_t)nn * C_IN + j0 + j];
            xs[j][n] = v;
        }
#pragma unroll
        for (int k = 0; k < (64 * KT) / 256; k++) {
            int idx = tid + k * 256;
            int j = idx >> 6, c = idx & 63;
            float v = 0.f;
            if ((j0 + j) < C_IN) v = W1[(size_t)(j0 + j) * 64 + c];
            Ws[j][c] = v;
        }
        __syncthreads();
#pragma unroll
        for (int j = 0; j < KT; j++) {
            float4 a = *(const float4*)&xs[j][n0];
            uint64_t b0 = *(const uint64_t*)&Ws[j][c0];
            uint64_t b1 = *(const uint64_t*)&Ws[j][c0 + 2];
            uint64_t ax = pack2(a.x, a.x), ay = pack2(a.y, a.y);
            uint64_t az = pack2(a.z, a.z), aw = pack2(a.w, a.w);
            ffma2(acc[0][0], ax, b0); ffma2(acc[0][1], ax, b1);
            ffma2(acc[1][0], ay, b0); ffma2(acc[1][1], ay, b1);
            ffma2(acc[2][0], az, b0); ffma2(acc[2][1], az, b1);
            ffma2(acc[3][0], aw, b0); ffma2(acc[3][1], aw, b1);
        }
        __syncthreads();
    }

    // att vectors for my 4 columns (flat [head][dim] == col index)
    float4 us = *(const float4*)&att_src[c0];
    float4 ud = *(const float4*)&att_dst[c0];
    int lane = tid & 31;
    int head = (lane & 15) >> 2;   // quad within 16-lane half = head

    float pas[4], pad[4];
#pragma unroll
    for (int i = 0; i < 4; i++) {
        float2 lo = unpack2(acc[i][0]), hi = unpack2(acc[i][1]);
        int n = nb + n0 + i;
        if (n < N) {
            __half2 h2a = __floats2half2_rn(lo.x, lo.y);
            __half2 h2b = __floats2half2_rn(hi.x, hi.y);
            uint2 pk;
            pk.x = *(uint32_t*)&h2a;
            pk.y = *(uint32_t*)&h2b;
            *(uint2*)&g_hh[(size_t)n * C1 + c0] = pk;
        }
        pas[i] = lo.x * us.x + lo.y * us.y + hi.x * us.z + hi.y * us.w;
        pad[i] = lo.x * ud.x + lo.y * ud.y + hi.x * ud.z + hi.y * ud.w;
    }
    // reduce across the 4 lanes of each head-quad
#pragma unroll
    for (int off = 1; off <= 2; off <<= 1) {
#pragma unroll
        for (int i = 0; i < 4; i++) {
            pas[i] += __shfl_xor_sync(0xffffffffu, pas[i], off);
            pad[i] += __shfl_xor_sync(0xffffffffu, pad[i], off);
        }
    }
    if ((lane & 3) == 0) {
#pragma unroll
        for (int i = 0; i < 4; i++) {
            int n = nb + n0 + i;
            if (n < N) {
                g_as[(size_t)n * 4 + head] = pas[i];
                g_ad[(size_t)n * 4 + head] = pad[i];
            }
        }
    }
}

// ---------------- CSR build: hist / scans / scatter ----------------
__global__ void k_hist(const int* __restrict__ ei, long long E,
                       int* __restrict__ deg, const int* flag) {
    long long e = (long long)blockIdx.x * blockDim.x + threadIdx.x;
    if (e >= E) return;
    int dst = *flag ? (int)((const long long*)ei)[E + e] : ei[(size_t)(E + e)];
    atomicAdd(&deg[dst], 1);
}
__global__ void k_bsum(const int* __restrict__ deg, int n, int* __restrict__ bsum) {
    __shared__ int s[256];
    int i = blockIdx.x * 256 + threadIdx.x;
    s[threadIdx.x] = (i < n) ? deg[i] : 0;
    __syncthreads();
    for (int off = 128; off > 0; off >>= 1) {
        if (threadIdx.x < off) s[threadIdx.x] += s[threadIdx.x + off];
        __syncthreads();
    }
    if (threadIdx.x == 0) bsum[blockIdx.x] = s[0];
}
__global__ void k_topscan(int* __restrict__ bs, int nb_) {
    __shared__ int s[512];
    int t = threadIdx.x;
    int v = (t < nb_) ? bs[t] : 0;
    s[t] = v;
    __syncthreads();
    for (int off = 1; off < 512; off <<= 1) {
        int x = (t >= off) ? s[t - off] : 0;
        __syncthreads();
        s[t] += x;
        __syncthreads();
    }
    if (t < nb_) bs[t] = s[t] - v;   // exclusive
}
__global__ void k_rowoff(const int* __restrict__ deg, const int* __restrict__ bsumex,
                         int* __restrict__ roff, int* __restrict__ cur, int n) {
    __shared__ int s[256];
    int t = threadIdx.x;
    int i = blockIdx.x * 256 + t;
    int v = (i < n) ? deg[i] : 0;
    s[t] = v;
    __syncthreads();
    for (int off = 1; off < 256; off <<= 1) {
        int x = (t >= off) ? s[t - off] : 0;
        __syncthreads();
        s[t] += x;
        __syncthreads();
    }
    int o = bsumex[blockIdx.x] + s[t] - v;
    if (i < n) { roff[i] = o; cur[i] = o; }
}
__global__ void k_scatter(const int* __restrict__ ei, long long E, const int* flag,
                          int* __restrict__ cur, int* __restrict__ csr) {
    long long e = (long long)blockIdx.x * blockDim.x + threadIdx.x;
    if (e >= E) return;
    int src, dst;
    load_edge(ei, E, e, *flag, src, dst);
    int pos = atomicAdd(&cur[dst], 1);
    csr[pos] = src;
}

// ---------------- GAT gather: warp per dst, fp16 rows, 8x unrolled ----------
__global__ void k_gat_gather(const float* __restrict__ b1, int N) {
    int n = (blockIdx.x * blockDim.x + threadIdx.x) >> 5;
    int lane = threadIdx.x & 31;
    if (n >= N) return;
    int head = lane >> 3;
    float adv = g_ad[n * 4 + head];
    float w = __expf(leaky(g_as[n * 4 + head] + adv));   // self loop
    float2 hv = __half22float2(*(const __half2*)&g_hh[(size_t)n * C1 + lane * 2]);
    float den = w;
    float ax = w * hv.x, ay = w * hv.y;
    int roff = g_roffa[n];
    int deg  = g_dega[n];
    int j = 0;
    for (; j + 8 <= deg; j += 8) {
        int s[8];
#pragma unroll
        for (int q = 0; q < 8; q++) s[q] = __ldg(&g_csra[roff + j + q]);
        float2 hq[8];
#pragma unroll
        for (int q = 0; q < 8; q++)
            hq[q] = __half22float2(*(const __half2*)&g_hh[(size_t)s[q] * C1 + lane * 2]);
        float eq[8];
#pragma unroll
        for (int q = 0; q < 8; q++) eq[q] = g_as[s[q] * 4 + head];
        float wq[8];
#pragma unroll
        for (int q = 0; q < 8; q++) wq[q] = __expf(leaky(eq[q] + adv));
#pragma unroll
        for (int q = 0; q < 8; q++) {
            den += wq[q];
            ax += wq[q] * hq[q].x;
            ay += wq[q] * hq[q].y;
        }
    }
    for (; j < deg; j++) {
        int s0 = __ldg(&g_csra[roff + j]);
        float w0 = __expf(leaky(g_as[s0 * 4 + head] + adv));
        float2 h0 = __half22float2(*(const __half2*)&g_hh[(size_t)s0 * C1 + lane * 2]);
        den += w0;
        ax += w0 * h0.x;
        ay += w0 * h0.y;
    }
    float r = 1.f / den;
    float2 bv = *(const float2*)&b1[lane * 2];
    float2 o;
    o.x = fmaxf(ax * r + bv.x, 0.f);
    o.y = fmaxf(ay * r + bv.y, 0.f);
    *(float2*)&g_x1[(size_t)n * C1 + lane * 2] = o;
}

// ---------------- GCN prep: h2 = x1 @ W2 (fp32 + fp16 mirror), dinv ----------
__global__ void k_gcn_prep(const float* __restrict__ W2, int N) {
    __shared__ float Wsh[C1 * OUT2];
    int tid = threadIdx.x;
    for (int i = tid; i < C1 * OUT2; i += blockDim.x) Wsh[i] = W2[i];
    __syncthreads();
    int warp = tid >> 5, lane = tid & 31;
    int n = blockIdx.x * (blockDim.x >> 5) + warp;
    if (n >= N) return;
    if (lane == 0) g_dinv[n] = rsqrtf((float)(g_degb[n] + 1));
    float acc = 0.f;
#pragma unroll
    for (int k = 0; k < C1; k++)
        acc += g_x1[(size_t)n * C1 + k] * Wsh[k * OUT2 + lane];
    g_h2[(size_t)n * OUT2 + lane] = acc;
    g_h2h[(size_t)n * OUT2 + lane] = __float2half_rn(acc);
}

// ---------------- GCN gather: warp per dst, fp16 rows, 8x ----------
__global__ void k_gcn_gather(const float* __restrict__ b2,
                             float* __restrict__ out, int N) {
    int n = (blockIdx.x * blockDim.x + threadIdx.x) >> 5;
    int lane = threadIdx.x & 31;
    if (n >= N) return;
    float dv = g_dinv[n];
    float acc = b2[lane] + dv * dv * g_h2[(size_t)n * OUT2 + lane];  // fp32 self
    int roff = g_roffb[n];
    int deg  = g_degb[n];
    int j = 0;
    for (; j + 8 <= deg; j += 8) {
        int s[8];
#pragma unroll
        for (int q = 0; q < 8; q++) s[q] = __ldg(&g_csrb[roff + j + q]);
        float v[8], d[8];
#pragma unroll
        for (int q = 0; q < 8; q++) v[q] = __half2float(g_h2h[(size_t)s[q] * OUT2 + lane]);
#pragma unroll
        for (int q = 0; q < 8; q++) d[q] = g_dinv[s[q]];
#pragma unroll
        for (int q = 0; q < 8; q++) acc += d[q] * v[q] * dv;
    }
    for (; j < deg; j++) {
        int s0 = __ldg(&g_csrb[roff + j]);
        acc += g_dinv[s0] * dv * __half2float(g_h2h[(size_t)s0 * OUT2 + lane]);
    }
    out[(size_t)n * OUT2 + lane] = acc;
}

// ---------------- launch (legal capture fork; static resources) ----------------
extern "C" void kernel_launch(void* const* d_in, const int* in_sizes, int n_in,
                              void* d_out, int out_size) {
    const float* x       = (const float*)d_in[0];
    const float* W1      = (const float*)d_in[1];
    const float* att_src = (const float*)d_in[2];
    const float* att_dst = (const float*)d_in[3];
    const float* b1      = (const float*)d_in[4];
    const float* W2      = (const float*)d_in[5];
    const float* b2      = (const float*)d_in[6];
    const int* ei        = (const int*)d_in[7];
    const int* sei       = (const int*)d_in[8];
    float* out = (float*)d_out;

    int N = in_sizes[0] / C_IN;
    long long E  = in_sizes[7] / 2;
    long long E2 = in_sizes[8] / 2;
    int nb = (N + 255) / 256;

    int *p_dega, *p_degb, *p_roffa, *p_roffb, *p_cura, *p_curb;
    int *p_csra, *p_csrb, *p_bsa, *p_bsb, *p_fa, *p_fb;
    cudaGetSymbolAddress((void**)&p_dega, g_dega);
    cudaGetSymbolAddress((void**)&p_degb, g_degb);
    cudaGetSymbolAddress((void**)&p_roffa, g_roffa);
    cudaGetSymbolAddress((void**)&p_roffb, g_roffb);
    cudaGetSymbolAddress((void**)&p_cura, g_cura);
    cudaGetSymbolAddress((void**)&p_curb, g_curb);
    cudaGetSymbolAddress((void**)&p_csra, g_csra);
    cudaGetSymbolAddress((void**)&p_csrb, g_csrb);
    cudaGetSymbolAddress((void**)&p_bsa, g_bsa);
    cudaGetSymbolAddress((void**)&p_bsb, g_bsb);
    cudaGetSymbolAddress((void**)&p_fa, g_is64_a);
    cudaGetSymbolAddress((void**)&p_fb, g_is64_b);

    // created once on the correctness call; reused thereafter (no alloc in capture)
    static cudaStream_t s1 = nullptr, s2 = nullptr;
    static cudaEvent_t evF = nullptr, evD = nullptr, evA = nullptr, evB = nullptr;
    if (!s1) {
        cudaStreamCreateWithFlags(&s1, cudaStreamNonBlocking);
        cudaStreamCreateWithFlags(&s2, cudaStreamNonBlocking);
        cudaEventCreateWithFlags(&evF, cudaEventDisableTiming);
        cudaEventCreateWithFlags(&evD, cudaEventDisableTiming);
        cudaEventCreateWithFlags(&evA, cudaEventDisableTiming);
        cudaEventCreateWithFlags(&evB, cudaEventDisableTiming);
    }

    // Fork point recorded on the ORIGIN (capture) stream — side streams must
    // join the capture by waiting on an origin-stream event before any work.
    cudaEventRecord(evF, 0);
    cudaStreamWaitEvent(s1, evF, 0);

    // branch S1: detect, then GAT CSR
    k_detect<<<1, 128, 0, s1>>>(ei, sei);
    cudaEventRecord(evD, s1);
    cudaStreamWaitEvent(s2, evD, 0);   // S2 forks off S1 after detect

    k_zero<<<nb, 256, 0, s1>>>(p_dega, N);
    k_hist<<<(unsigned)((E + 255) / 256), 256, 0, s1>>>(ei, E, p_dega, p_fa);
    k_bsum<<<nb, 256, 0, s1>>>(p_dega, N, p_bsa);
    k_topscan<<<1, 512, 0, s1>>>(p_bsa, nb);
    k_rowoff<<<nb, 256, 0, s1>>>(p_dega, p_bsa, p_roffa, p_cura, N);
    k_scatter<<<(unsigned)((E + 255) / 256), 256, 0, s1>>>(ei, E, p_fa, p_cura, p_csra);
    cudaEventRecord(evA, s1);

    // branch S2: GCN CSR
    k_zero<<<nb, 256, 0, s2>>>(p_degb, N);
    k_hist<<<(unsigned)((E2 + 255) / 256), 256, 0, s2>>>(sei, E2, p_degb, p_fb);
    k_bsum<<<nb, 256, 0, s2>>>(p_degb, N, p_bsb);
    k_topscan<<<1, 512, 0, s2>>>(p_bsb, nb);
    k_rowoff<<<nb, 256, 0, s2>>>(p_degb, p_bsb, p_roffb, p_curb, N);
    k_scatter<<<(unsigned)((E2 + 255) / 256), 256, 0, s2>>>(sei, E2, p_fb, p_curb, p_csrb);
    cudaEventRecord(evB, s2);

    // origin stream: dense compute with fused attention (starts immediately)
    k_gemm1<<<(N + 63) / 64, 256>>>(x, W1, att_src, att_dst, N);

    cudaStreamWaitEvent(0, evA, 0);
    k_gat_gather<<<(N * 32 + 255) / 256, 256>>>(b1, N);
    cudaStreamWaitEvent(0, evB, 0);
    k_gcn_prep<<<(N + 7) / 8, 256>>>(W2, N);
    k_gcn_gather<<<(N * 32 + 255) / 256, 256>>>(b2, out, N);
}

// round 10
// speedup vs baseline: 1.0552x; 1.0552x over previous
#include <cuda_runtime.h>
#include <cuda_fp16.h>
#include <cstdint>

#define NMAX   100352
#define EMAX   3276800
#define C_IN   300
#define C1     64
#define HEADS  4
#define OUT2   32
#define SLOPE  0.2f

// ---------------- device scratch ----------------
__device__ __align__(16) __half g_hh[(size_t)NMAX * C1];    // x@W1 fp16     [N,64]
__device__ __align__(16) float  g_x1[(size_t)NMAX * C1];    // relu(GAT)+b1  [N,64]
__device__ __align__(16) float  g_as[(size_t)NMAX * HEADS];
__device__ __align__(16) float  g_ad[(size_t)NMAX * HEADS];
__device__ __align__(16) __half g_h2s[(size_t)NMAX * OUT2]; // dinv*(x1@W2)  [N,32] fp16
__device__ __align__(16) float  g_dinv[NMAX];
__device__ int g_dega[NMAX], g_degb[NMAX];
__device__ int g_roffa[NMAX], g_roffb[NMAX];
__device__ int g_cura[NMAX],  g_curb[NMAX];
__device__ int g_csra[EMAX],  g_csrb[EMAX];
__device__ int g_bsa[1024],   g_bsb[1024];
__device__ int g_is64_a, g_is64_b;

__device__ __forceinline__ float leaky(float v) { return v > 0.f ? v : SLOPE * v; }

__device__ __forceinline__ uint64_t pack2(float lo, float hi) {
    uint64_t r; asm("mov.b64 %0,{%1,%2};" : "=l"(r) : "f"(lo), "f"(hi)); return r;
}
__device__ __forceinline__ float2 unpack2(uint64_t v) {
    float2 f; asm("mov.b64 {%0,%1},%2;" : "=f"(f.x), "=f"(f.y) : "l"(v)); return f;
}
__device__ __forceinline__ void ffma2(uint64_t& d, uint64_t a, uint64_t b) {
    asm("fma.rn.f32x2 %0, %1, %2, %0;" : "+l"(d) : "l"(a), "l"(b));
}

__device__ __forceinline__ void load_edge(const int* __restrict__ ei,
                                          long long E, long long e, int is64,
                                          int& src, int& dst) {
    if (is64) {
        src = (int)((const long long*)ei)[e];
        dst = (int)((const long long*)ei)[E + e];
    } else {
        src = ei[(size_t)e];
        dst = ei[(size_t)(E + e)];
    }
}

// ---------------- K0: detect edge dtype ----------------
__global__ void k_detect(const int* __restrict__ a, const int* __restrict__ b) {
    __shared__ int sa, sb;
    if (threadIdx.x == 0) { sa = 0; sb = 0; }
    __syncthreads();
    atomicOr(&sa, a[2 * threadIdx.x + 1]);
    atomicOr(&sb, b[2 * threadIdx.x + 1]);
    __syncthreads();
    if (threadIdx.x == 0) {
        g_is64_a = (sa == 0) ? 1 : 0;
        g_is64_b = (sb == 0) ? 1 : 0;
    }
}
__global__ void k_zero(int* __restrict__ deg, int n) {
    int i = blockIdx.x * blockDim.x + threadIdx.x;
    if (i < n) deg[i] = 0;
}

// ---------------- K1: h = x @ W1 (f32x2) + fused attn reduction ----------
#define KT 64
__global__ void k_gemm1(const float* __restrict__ x,
                        const float* __restrict__ W1,
                        const float* __restrict__ att_src,
                        const float* __restrict__ att_dst, int N) {
    __shared__ float xs[KT][68];
    __shared__ float Ws[KT][64];
    const int tid = threadIdx.x;
    const int nb  = blockIdx.x * 64;
    const int n0  = (tid >> 4) * 4;
    const int c0  = (tid & 15) * 4;

    uint64_t acc[4][2];
#pragma unroll
    for (int i = 0; i < 4; i++) { acc[i][0] = pack2(0.f, 0.f); acc[i][1] = pack2(0.f, 0.f); }

    for (int j0 = 0; j0 < C_IN; j0 += KT) {
#pragma unroll
        for (int k = 0; k < (64 * KT) / 256; k++) {
            int idx = tid + k * 256;
            int n = idx / KT, j = idx % KT;
            int nn = nb + n;
            float v = 0.f;
            if ((j0 + j) < C_IN && nn < N) v = x[(size_t)nn * C_IN + j0 + j];
            xs[j][n] = v;
        }
#pragma unroll
        for (int k = 0; k < (64 * KT) / 256; k++) {
            int idx = tid + k * 256;
            int j = idx >> 6, c = idx & 63;
            float v = 0.f;
            if ((j0 + j) < C_IN) v = W1[(size_t)(j0 + j) * 64 + c];
            Ws[j][c] = v;
        }
        __syncthreads();
#pragma unroll
        for (int j = 0; j < KT; j++) {
            float4 a = *(const float4*)&xs[j][n0];
            uint64_t b0 = *(const uint64_t*)&Ws[j][c0];
            uint64_t b1 = *(const uint64_t*)&Ws[j][c0 + 2];
            uint64_t ax = pack2(a.x, a.x), ay = pack2(a.y, a.y);
            uint64_t az = pack2(a.z, a.z), aw = pack2(a.w, a.w);
            ffma2(acc[0][0], ax, b0); ffma2(acc[0][1], ax, b1);
            ffma2(acc[1][0], ay, b0); ffma2(acc[1][1], ay, b1);
            ffma2(acc[2][0], az, b0); ffma2(acc[2][1], az, b1);
            ffma2(acc[3][0], aw, b0); ffma2(acc[3][1], aw, b1);
        }
        __syncthreads();
    }

    // att vectors for my 4 columns (flat [head][dim] == col index)
    float4 us = *(const float4*)&att_src[c0];
    float4 ud = *(const float4*)&att_dst[c0];
    int lane = tid & 31;
    int head = (lane & 15) >> 2;   // quad within 16-lane half = head

    float pas[4], pad[4];
#pragma unroll
    for (int i = 0; i < 4; i++) {
        float2 lo = unpack2(acc[i][0]), hi = unpack2(acc[i][1]);
        int n = nb + n0 + i;
        if (n < N) {
            __half2 h2a = __floats2half2_rn(lo.x, lo.y);
            __half2 h2b = __floats2half2_rn(hi.x, hi.y);
            uint2 pk;
            pk.x = *(uint32_t*)&h2a;
            pk.y = *(uint32_t*)&h2b;
            *(uint2*)&g_hh[(size_t)n * C1 + c0] = pk;
        }
        pas[i] = lo.x * us.x + lo.y * us.y + hi.x * us.z + hi.y * us.w;
        pad[i] = lo.x * ud.x + lo.y * ud.y + hi.x * ud.z + hi.y * ud.w;
    }
    // reduce across the 4 lanes of each head-quad
#pragma unroll
    for (int off = 1; off <= 2; off <<= 1) {
#pragma unroll
        for (int i = 0; i < 4; i++) {
            pas[i] += __shfl_xor_sync(0xffffffffu, pas[i], off);
            pad[i] += __shfl_xor_sync(0xffffffffu, pad[i], off);
        }
    }
    if ((lane & 3) == 0) {
#pragma unroll
        for (int i = 0; i < 4; i++) {
            int n = nb + n0 + i;
            if (n < N) {
                g_as[(size_t)n * 4 + head] = pas[i];
                g_ad[(size_t)n * 4 + head] = pad[i];
            }
        }
    }
}

// ---------------- CSR build: hist / scans / scatter ----------------
__global__ void k_hist(const int* __restrict__ ei, long long E,
                       int* __restrict__ deg, const int* flag) {
    long long e = (long long)blockIdx.x * blockDim.x + threadIdx.x;
    if (e >= E) return;
    int dst = *flag ? (int)((const long long*)ei)[E + e] : ei[(size_t)(E + e)];
    atomicAdd(&deg[dst], 1);
}
__global__ void k_bsum(const int* __restrict__ deg, int n, int* __restrict__ bsum) {
    __shared__ int s[256];
    int i = blockIdx.x * 256 + threadIdx.x;
    s[threadIdx.x] = (i < n) ? deg[i] : 0;
    __syncthreads();
    for (int off = 128; off > 0; off >>= 1) {
        if (threadIdx.x < off) s[threadIdx.x] += s[threadIdx.x + off];
        __syncthreads();
    }
    if (threadIdx.x == 0) bsum[blockIdx.x] = s[0];
}
__global__ void k_topscan(int* __restrict__ bs, int nb_) {
    __shared__ int s[512];
    int t = threadIdx.x;
    int v = (t < nb_) ? bs[t] : 0;
    s[t] = v;
    __syncthreads();
    for (int off = 1; off < 512; off <<= 1) {
        int x = (t >= off) ? s[t - off] : 0;
        __syncthreads();
        s[t] += x;
        __syncthreads();
    }
    if (t < nb_) bs[t] = s[t] - v;   // exclusive
}
__global__ void k_rowoff(const int* __restrict__ deg, const int* __restrict__ bsumex,
                         int* __restrict__ roff, int* __restrict__ cur, int n) {
    __shared__ int s[256];
    int t = threadIdx.x;
    int i = blockIdx.x * 256 + t;
    int v = (i < n) ? deg[i] : 0;
    s[t] = v;
    __syncthreads();
    for (int off = 1; off < 256; off <<= 1) {
        int x = (t >= off) ? s[t - off] : 0;
        __syncthreads();
        s[t] += x;
        __syncthreads();
    }
    int o = bsumex[blockIdx.x] + s[t] - v;
    if (i < n) { roff[i] = o; cur[i] = o; }
}
__global__ void k_scatter(const int* __restrict__ ei, long long E, const int* flag,
                          int* __restrict__ cur, int* __restrict__ csr) {
    long long e = (long long)blockIdx.x * blockDim.x + threadIdx.x;
    if (e >= E) return;
    int src, dst;
    load_edge(ei, E, e, *flag, src, dst);
    int pos = atomicAdd(&cur[dst], 1);
    csr[pos] = src;
}

// ---------------- GAT gather: warp per dst, fp16 rows, 4x unrolled ----------
__global__ void k_gat_gather(const float* __restrict__ b1, int N) {
    int n = (blockIdx.x * blockDim.x + threadIdx.x) >> 5;
    int lane = threadIdx.x & 31;
    if (n >= N) return;
    int head = lane >> 3;
    float adv = g_ad[n * 4 + head];
    float w = __expf(leaky(g_as[n * 4 + head] + adv));   // self loop
    float2 hv = __half22float2(*(const __half2*)&g_hh[(size_t)n * C1 + lane * 2]);
    float den = w;
    float ax = w * hv.x, ay = w * hv.y;
    int roff = g_roffa[n];
    int deg  = g_dega[n];
    int j = 0;
    for (; j + 4 <= deg; j += 4) {
        int s0 = __ldg(&g_csra[roff + j + 0]);
        int s1 = __ldg(&g_csra[roff + j + 1]);
        int s2 = __ldg(&g_csra[roff + j + 2]);
        int s3 = __ldg(&g_csra[roff + j + 3]);
        float2 h0 = __half22float2(*(const __half2*)&g_hh[(size_t)s0 * C1 + lane * 2]);
        float2 h1 = __half22float2(*(const __half2*)&g_hh[(size_t)s1 * C1 + lane * 2]);
        float2 h2 = __half22float2(*(const __half2*)&g_hh[(size_t)s2 * C1 + lane * 2]);
        float2 h3 = __half22float2(*(const __half2*)&g_hh[(size_t)s3 * C1 + lane * 2]);
        float e0 = g_as[s0 * 4 + head];
        float e1 = g_as[s1 * 4 + head];
        float e2 = g_as[s2 * 4 + head];
        float e3 = g_as[s3 * 4 + head];
        float w0 = __expf(leaky(e0 + adv));
        float w1 = __expf(leaky(e1 + adv));
        float w2 = __expf(leaky(e2 + adv));
        float w3 = __expf(leaky(e3 + adv));
        den += (w0 + w1) + (w2 + w3);
        ax += w0 * h0.x + w1 * h1.x + w2 * h2.x + w3 * h3.x;
        ay += w0 * h0.y + w1 * h1.y + w2 * h2.y + w3 * h3.y;
    }
    for (; j < deg; j++) {
        int s0 = __ldg(&g_csra[roff + j]);
        float w0 = __expf(leaky(g_as[s0 * 4 + head] + adv));
        float2 h0 = __half22float2(*(const __half2*)&g_hh[(size_t)s0 * C1 + lane * 2]);
        den += w0;
        ax += w0 * h0.x;
        ay += w0 * h0.y;
    }
    float r = 1.f / den;
    float2 bv = *(const float2*)&b1[lane * 2];
    float2 o;
    o.x = fmaxf(ax * r + bv.x, 0.f);
    o.y = fmaxf(ay * r + bv.y, 0.f);
    *(float2*)&g_x1[(size_t)n * C1 + lane * 2] = o;
}

// ---------------- GCN prep: h2s = dinv*(x1 @ W2) fp16, dinv ----------
__global__ void k_gcn_prep(const float* __restrict__ W2, int N) {
    __shared__ float Wsh[C1 * OUT2];
    int tid = threadIdx.x;
    for (int i = tid; i < C1 * OUT2; i += blockDim.x) Wsh[i] = W2[i];
    __syncthreads();
    int warp = tid >> 5, lane = tid & 31;
    int n = blockIdx.x * (blockDim.x >> 5) + warp;
    if (n >= N) return;
    float dv = rsqrtf((float)(g_degb[n] + 1));
    if (lane == 0) g_dinv[n] = dv;
    float acc = 0.f;
#pragma unroll
    for (int k = 0; k < C1; k++)
        acc += g_x1[(size_t)n * C1 + k] * Wsh[k * OUT2 + lane];
    g_h2s[(size_t)n * OUT2 + lane] = __float2half_rn(acc * dv);
}

// ---------------- GCN gather: warp per dst, 2 LDG/edge, 8x ----------
// out[n] = b2 + dinv[n] * ( h2s[n] + sum_{src} h2s[src] )
__global__ void k_gcn_gather(const float* __restrict__ b2,
                             float* __restrict__ out, int N) {
    int n = (blockIdx.x * blockDim.x + threadIdx.x) >> 5;
    int lane = threadIdx.x & 31;
    if (n >= N) return;
    float dv = g_dinv[n];
    float acc = __half2float(g_h2s[(size_t)n * OUT2 + lane]);  // self term
    int roff = g_roffb[n];
    int deg  = g_degb[n];
    int j = 0;
    for (; j + 8 <= deg; j += 8) {
        int s[8];
#pragma unroll
        for (int q = 0; q < 8; q++) s[q] = __ldg(&g_csrb[roff + j + q]);
        float v[8];
#pragma unroll
        for (int q = 0; q < 8; q++) v[q] = __half2float(g_h2s[(size_t)s[q] * OUT2 + lane]);
#pragma unroll
        for (int q = 0; q < 8; q++) acc += v[q];
    }
    for (; j < deg; j++) {
        int s0 = __ldg(&g_csrb[roff + j]);
        acc += __half2float(g_h2s[(size_t)s0 * OUT2 + lane]);
    }
    out[(size_t)n * OUT2 + lane] = b2[lane] + dv * acc;
}

// ---------------- launch (R7 topology; static resources) ----------------
extern "C" void kernel_launch(void* const* d_in, const int* in_sizes, int n_in,
                              void* d_out, int out_size) {
    const float* x       = (const float*)d_in[0];
    const float* W1      = (const float*)d_in[1];
    const float* att_src = (const float*)d_in[2];
    const float* att_dst = (const float*)d_in[3];
    const float* b1      = (const float*)d_in[4];
    const float* W2      = (const float*)d_in[5];
    const float* b2      = (const float*)d_in[6];
    const int* ei        = (const int*)d_in[7];
    const int* sei       = (const int*)d_in[8];
    float* out = (float*)d_out;

    int N = in_sizes[0] / C_IN;
    long long E  = in_sizes[7] / 2;
    long long E2 = in_sizes[8] / 2;
    int nb = (N + 255) / 256;

    int *p_dega, *p_degb, *p_roffa, *p_roffb, *p_cura, *p_curb;
    int *p_csra, *p_csrb, *p_bsa, *p_bsb, *p_fa, *p_fb;
    cudaGetSymbolAddress((void**)&p_dega, g_dega);
    cudaGetSymbolAddress((void**)&p_degb, g_degb);
    cudaGetSymbolAddress((void**)&p_roffa, g_roffa);
    cudaGetSymbolAddress((void**)&p_roffb, g_roffb);
    cudaGetSymbolAddress((void**)&p_cura, g_cura);
    cudaGetSymbolAddress((void**)&p_curb, g_curb);
    cudaGetSymbolAddress((void**)&p_csra, g_csra);
    cudaGetSymbolAddress((void**)&p_csrb, g_csrb);
    cudaGetSymbolAddress((void**)&p_bsa, g_bsa);
    cudaGetSymbolAddress((void**)&p_bsb, g_bsb);
    cudaGetSymbolAddress((void**)&p_fa, g_is64_a);
    cudaGetSymbolAddress((void**)&p_fb, g_is64_b);

    // created once on the correctness call; reused thereafter (no alloc in capture)
    static cudaStream_t s1 = nullptr, s2 = nullptr;
    static cudaEvent_t evF = nullptr, evA = nullptr, evB = nullptr;
    if (!s1) {
        cudaStreamCreateWithFlags(&s1, cudaStreamNonBlocking);
        cudaStreamCreateWithFlags(&s2, cudaStreamNonBlocking);
        cudaEventCreateWithFlags(&evF, cudaEventDisableTiming);
        cudaEventCreateWithFlags(&evA, cudaEventDisableTiming);
        cudaEventCreateWithFlags(&evB, cudaEventDisableTiming);
    }

    // detect on origin stream first (both CSR branches need the dtype flags)
    k_detect<<<1, 128>>>(ei, sei);
    cudaEventRecord(evF, 0);
    cudaStreamWaitEvent(s1, evF, 0);
    cudaStreamWaitEvent(s2, evF, 0);

    // branch S1: GAT CSR
    k_zero<<<nb, 256, 0, s1>>>(p_dega, N);
    k_hist<<<(unsigned)((E + 255) / 256), 256, 0, s1>>>(ei, E, p_dega, p_fa);
    k_bsum<<<nb, 256, 0, s1>>>(p_dega, N, p_bsa);
    k_topscan<<<1, 512, 0, s1>>>(p_bsa, nb);
    k_rowoff<<<nb, 256, 0, s1>>>(p_dega, p_bsa, p_roffa, p_cura, N);
    k_scatter<<<(unsigned)((E + 255) / 256), 256, 0, s1>>>(ei, E, p_fa, p_cura, p_csra);
    cudaEventRecord(evA, s1);

    // branch S2: GCN CSR
    k_zero<<<nb, 256, 0, s2>>>(p_degb, N);
    k_hist<<<(unsigned)((E2 + 255) / 256), 256, 0, s2>>>(sei, E2, p_degb, p_fb);
    k_bsum<<<nb, 256, 0, s2>>>(p_degb, N, p_bsb);
    k_topscan<<<1, 512, 0, s2>>>(p_bsb, nb);
    k_rowoff<<<nb, 256, 0, s2>>>(p_degb, p_bsb, p_roffb, p_curb, N);
    k_scatter<<<(unsigned)((E2 + 255) / 256), 256, 0, s2>>>(sei, E2, p_fb, p_curb, p_csrb);
    cudaEventRecord(evB, s2);

    // origin stream: dense compute with fused attention
    k_gemm1<<<(N + 63) / 64, 256>>>(x, W1, att_src, att_dst, N);

    cudaStreamWaitEvent(0, evA, 0);
    k_gat_gather<<<(N * 32 + 255) / 256, 256>>>(b1, N);
    cudaStreamWaitEvent(0, evB, 0);
    k_gcn_prep<<<(N + 7) / 8, 256>>>(W2, N);
    k_gcn_gather<<<(N * 32 + 255) / 256, 256>>>(b2, out, N);
}

// round 11
// speedup vs baseline: 1.0744x; 1.0182x over previous
#include <cuda_runtime.h>
#include <cuda_fp16.h>
#include <cstdint>

#define NMAX   100352
#define EMAX   3276800
#define CSRMAX (EMAX + 4 * NMAX)   // degree padded to multiple of 4 per node
#define C_IN   300
#define C1     64
#define HEADS  4
#define OUT2   32
#define SLOPE  0.2f

// ---------------- device scratch ----------------
__device__ __align__(16) __half g_hh[(size_t)NMAX * C1];    // x@W1 fp16     [N,64]
__device__ __align__(16) float  g_x1[(size_t)NMAX * C1];    // relu(GAT)+b1  [N,64]
__device__ __align__(16) float  g_as[(size_t)NMAX * HEADS];
__device__ __align__(16) float  g_ad[(size_t)NMAX * HEADS];
__device__ __align__(16) __half g_h2s[(size_t)NMAX * OUT2]; // dinv*(x1@W2)  [N,32] fp16
__device__ __align__(16) float  g_dinv[NMAX];
__device__ int g_dega[NMAX], g_degb[NMAX];
__device__ int g_roffa[NMAX], g_roffb[NMAX];
__device__ int g_cura[NMAX],  g_curb[NMAX];
__device__ __align__(16) int g_csra[CSRMAX];
__device__ __align__(16) int g_csrb[CSRMAX];
__device__ int g_bsa[1024],   g_bsb[1024];
__device__ int g_is64_a, g_is64_b;

__device__ __forceinline__ float leaky(float v) { return v > 0.f ? v : SLOPE * v; }

__device__ __forceinline__ uint64_t pack2(float lo, float hi) {
    uint64_t r; asm("mov.b64 %0,{%1,%2};" : "=l"(r) : "f"(lo), "f"(hi)); return r;
}
__device__ __forceinline__ float2 unpack2(uint64_t v) {
    float2 f; asm("mov.b64 {%0,%1},%2;" : "=f"(f.x), "=f"(f.y) : "l"(v)); return f;
}
__device__ __forceinline__ void ffma2(uint64_t& d, uint64_t a, uint64_t b) {
    asm("fma.rn.f32x2 %0, %1, %2, %0;" : "+l"(d) : "l"(a), "l"(b));
}

__device__ __forceinline__ void load_edge(const int* __restrict__ ei,
                                          long long E, long long e, int is64,
                                          int& src, int& dst) {
    if (is64) {
        src = (int)((const long long*)ei)[e];
        dst = (int)((const long long*)ei)[E + e];
    } else {
        src = ei[(size_t)e];
        dst = ei[(size_t)(E + e)];
    }
}

// ---------------- K0: detect edge dtype ----------------
__global__ void k_detect(const int* __restrict__ a, const int* __restrict__ b) {
    __shared__ int sa, sb;
    if (threadIdx.x == 0) { sa = 0; sb = 0; }
    __syncthreads();
    atomicOr(&sa, a[2 * threadIdx.x + 1]);
    atomicOr(&sb, b[2 * threadIdx.x + 1]);
    __syncthreads();
    if (threadIdx.x == 0) {
        g_is64_a = (sa == 0) ? 1 : 0;
        g_is64_b = (sb == 0) ? 1 : 0;
    }
}
__global__ void k_zero(int* __restrict__ deg, int n) {
    int i = blockIdx.x * blockDim.x + threadIdx.x;
    if (i < n) deg[i] = 0;
}

// ---------------- K1: h = x @ W1 (f32x2) + fused attn reduction ----------
#define KT 64
__global__ void k_gemm1(const float* __restrict__ x,
                        const float* __restrict__ W1,
                        const float* __restrict__ att_src,
                        const float* __restrict__ att_dst, int N) {
    __shared__ float xs[KT][68];
    __shared__ float Ws[KT][64];
    const int tid = threadIdx.x;
    const int nb  = blockIdx.x * 64;
    const int n0  = (tid >> 4) * 4;
    const int c0  = (tid & 15) * 4;

    uint64_t acc[4][2];
#pragma unroll
    for (int i = 0; i < 4; i++) { acc[i][0] = pack2(0.f, 0.f); acc[i][1] = pack2(0.f, 0.f); }

    for (int j0 = 0; j0 < C_IN; j0 += KT) {
#pragma unroll
        for (int k = 0; k < (64 * KT) / 256; k++) {
            int idx = tid + k * 256;
            int n = idx / KT, j = idx % KT;
            int nn = nb + n;
            float v = 0.f;
            if ((j0 + j) < C_IN && nn < N) v = x[(size_t)nn * C_IN + j0 + j];
            xs[j][n] = v;
        }
#pragma unroll
        for (int k = 0; k < (64 * KT) / 256; k++) {
            int idx = tid + k * 256;
            int j = idx >> 6, c = idx & 63;
            float v = 0.f;
            if ((j0 + j) < C_IN) v = W1[(size_t)(j0 + j) * 64 + c];
            Ws[j][c] = v;
        }
        __syncthreads();
#pragma unroll
        for (int j = 0; j < KT; j++) {
            float4 a = *(const float4*)&xs[j][n0];
            uint64_t b0 = *(const uint64_t*)&Ws[j][c0];
            uint64_t b1 = *(const uint64_t*)&Ws[j][c0 + 2];
            uint64_t ax = pack2(a.x, a.x), ay = pack2(a.y, a.y);
            uint64_t az = pack2(a.z, a.z), aw = pack2(a.w, a.w);
            ffma2(acc[0][0], ax, b0); ffma2(acc[0][1], ax, b1);
            ffma2(acc[1][0], ay, b0); ffma2(acc[1][1], ay, b1);
            ffma2(acc[2][0], az, b0); ffma2(acc[2][1], az, b1);
            ffma2(acc[3][0], aw, b0); ffma2(acc[3][1], aw, b1);
        }
        __syncthreads();
    }

    float4 us = *(const float4*)&att_src[c0];
    float4 ud = *(const float4*)&att_dst[c0];
    int lane = tid & 31;
    int head = (lane & 15) >> 2;

    float pas[4], pad[4];
#pragma unroll
    for (int i = 0; i < 4; i++) {
        float2 lo = unpack2(acc[i][0]), hi = unpack2(acc[i][1]);
        int n = nb + n0 + i;
        if (n < N) {
            __half2 h2a = __floats2half2_rn(lo.x, lo.y);
            __half2 h2b = __floats2half2_rn(hi.x, hi.y);
            uint2 pk;
            pk.x = *(uint32_t*)&h2a;
            pk.y = *(uint32_t*)&h2b;
            *(uint2*)&g_hh[(size_t)n * C1 + c0] = pk;
        }
        pas[i] = lo.x * us.x + lo.y * us.y + hi.x * us.z + hi.y * us.w;
        pad[i] = lo.x * ud.x + lo.y * ud.y + hi.x * ud.z + hi.y * ud.w;
    }
#pragma unroll
    for (int off = 1; off <= 2; off <<= 1) {
#pragma unroll
        for (int i = 0; i < 4; i++) {
            pas[i] += __shfl_xor_sync(0xffffffffu, pas[i], off);
            pad[i] += __shfl_xor_sync(0xffffffffu, pad[i], off);
        }
    }
    if ((lane & 3) == 0) {
#pragma unroll
        for (int i = 0; i < 4; i++) {
            int n = nb + n0 + i;
            if (n < N) {
                g_as[(size_t)n * 4 + head] = pas[i];
                g_ad[(size_t)n * 4 + head] = pad[i];
            }
        }
    }
}

// ---------------- CSR build (offsets padded to multiples of 4) ----------------
__global__ void k_hist(const int* __restrict__ ei, long long E,
                       int* __restrict__ deg, const int* flag) {
    long long e = (long long)blockIdx.x * blockDim.x + threadIdx.x;
    if (e >= E) return;
    int dst = *flag ? (int)((const long long*)ei)[E + e] : ei[(size_t)(E + e)];
    atomicAdd(&deg[dst], 1);
}
__global__ void k_bsum(const int* __restrict__ deg, int n, int* __restrict__ bsum) {
    __shared__ int s[256];
    int i = blockIdx.x * 256 + threadIdx.x;
    s[threadIdx.x] = (i < n) ? ((deg[i] + 3) & ~3) : 0;   // padded degree
    __syncthreads();
    for (int off = 128; off > 0; off >>= 1) {
        if (threadIdx.x < off) s[threadIdx.x] += s[threadIdx.x + off];
        __syncthreads();
    }
    if (threadIdx.x == 0) bsum[blockIdx.x] = s[0];
}
__global__ void k_topscan(int* __restrict__ bs, int nb_) {
    __shared__ int s[512];
    int t = threadIdx.x;
    int v = (t < nb_) ? bs[t] : 0;
    s[t] = v;
    __syncthreads();
    for (int off = 1; off < 512; off <<= 1) {
        int x = (t >= off) ? s[t - off] : 0;
        __syncthreads();
        s[t] += x;
        __syncthreads();
    }
    if (t < nb_) bs[t] = s[t] - v;   // exclusive
}
__global__ void k_rowoff(const int* __restrict__ deg, const int* __restrict__ bsumex,
                         int* __restrict__ roff, int* __restrict__ cur, int n) {
    __shared__ int s[256];
    int t = threadIdx.x;
    int i = blockIdx.x * 256 + t;
    int v = (i < n) ? ((deg[i] + 3) & ~3) : 0;   // padded degree
    s[t] = v;
    __syncthreads();
    for (int off = 1; off < 256; off <<= 1) {
        int x = (t >= off) ? s[t - off] : 0;
        __syncthreads();
        s[t] += x;
        __syncthreads();
    }
    int o = bsumex[blockIdx.x] + s[t] - v;       // 4-aligned offset
    if (i < n) { roff[i] = o; cur[i] = o; }
}
__global__ void k_scatter(const int* __restrict__ ei, long long E, const int* flag,
                          int* __restrict__ cur, int* __restrict__ csr) {
    long long e = (long long)blockIdx.x * blockDim.x + threadIdx.x;
    if (e >= E) return;
    int src, dst;
    load_edge(ei, E, e, *flag, src, dst);
    int pos = atomicAdd(&cur[dst], 1);
    csr[pos] = src;
}

// ---------------- GAT gather: warp per dst, int4 CSR, fp16 rows ----------
__global__ void k_gat_gather(const float* __restrict__ b1, int N) {
    int n = (blockIdx.x * blockDim.x + threadIdx.x) >> 5;
    int lane = threadIdx.x & 31;
    if (n >= N) return;
    int head = lane >> 3;
    float adv = g_ad[n * 4 + head];
    float w = __expf(leaky(g_as[n * 4 + head] + adv));   // self loop
    float2 hv = __half22float2(*(const __half2*)&g_hh[(size_t)n * C1 + lane * 2]);
    float den = w;
    float ax = w * hv.x, ay = w * hv.y;
    int roff = g_roffa[n];      // 16B-aligned
    int deg  = g_dega[n];
    int j = 0;
    for (; j + 4 <= deg; j += 4) {
        int4 ss = *(const int4*)&g_csra[roff + j];   // 4 srcs in one LDG.128
        float2 h0 = __half22float2(*(const __half2*)&g_hh[(size_t)ss.x * C1 + lane * 2]);
        float2 h1 = __half22float2(*(const __half2*)&g_hh[(size_t)ss.y * C1 + lane * 2]);
        float2 h2 = __half22float2(*(const __half2*)&g_hh[(size_t)ss.z * C1 + lane * 2]);
        float2 h3 = __half22float2(*(const __half2*)&g_hh[(size_t)ss.w * C1 + lane * 2]);
        float e0 = g_as[ss.x * 4 + head];
        float e1 = g_as[ss.y * 4 + head];
        float e2 = g_as[ss.z * 4 + head];
        float e3 = g_as[ss.w * 4 + head];
        float w0 = __expf(leaky(e0 + adv));
        float w1 = __expf(leaky(e1 + adv));
        float w2 = __expf(leaky(e2 + adv));
        float w3 = __expf(leaky(e3 + adv));
        den += (w0 + w1) + (w2 + w3);
        ax += w0 * h0.x + w1 * h1.x + w2 * h2.x + w3 * h3.x;
        ay += w0 * h0.y + w1 * h1.y + w2 * h2.y + w3 * h3.y;
    }
    if (j < deg) {
        int4 ss = *(const int4*)&g_csra[roff + j];   // padded slot: safe to load
        int rem = deg - j;
        int sv[3] = {ss.x, ss.y, ss.z};
        for (int q = 0; q < 3; q++) {
            if (q < rem) {
                int s0 = sv[q];
                float w0 = __expf(leaky(g_as[s0 * 4 + head] + adv));
                float2 h0 = __half22float2(*(const __half2*)&g_hh[(size_t)s0 * C1 + lane * 2]);
                den += w0;
                ax += w0 * h0.x;
                ay += w0 * h0.y;
            }
        }
    }
    float r = 1.f / den;
    float2 bv = *(const float2*)&b1[lane * 2];
    float2 o;
    o.x = fmaxf(ax * r + bv.x, 0.f);
    o.y = fmaxf(ay * r + bv.y, 0.f);
    *(float2*)&g_x1[(size_t)n * C1 + lane * 2] = o;
}

// ---------------- GCN prep: h2s = dinv*(x1 @ W2) fp16, dinv ----------
__global__ void k_gcn_prep(const float* __restrict__ W2, int N) {
    __shared__ float Wsh[C1 * OUT2];
    int tid = threadIdx.x;
    for (int i = tid; i < C1 * OUT2; i += blockDim.x) Wsh[i] = W2[i];
    __syncthreads();
    int warp = tid >> 5, lane = tid & 31;
    int n = blockIdx.x * (blockDim.x >> 5) + warp;
    if (n >= N) return;
    float dv = rsqrtf((float)(g_degb[n] + 1));
    if (lane == 0) g_dinv[n] = dv;
    float acc = 0.f;
#pragma unroll
    for (int k = 0; k < C1; k++)
        acc += g_x1[(size_t)n * C1 + k] * Wsh[k * OUT2 + lane];
    g_h2s[(size_t)n * OUT2 + lane] = __float2half_rn(acc * dv);
}

// ---------------- GCN gather: warp per dst, int4 CSR, 8-edge body ----------
// out[n] = b2 + dinv[n] * ( h2s[n] + sum_{src} h2s[src] )
__global__ void k_gcn_gather(const float* __restrict__ b2,
                             float* __restrict__ out, int N) {
    int n = (blockIdx.x * blockDim.x + threadIdx.x) >> 5;
    int lane = threadIdx.x & 31;
    if (n >= N) return;
    float dv = g_dinv[n];
    float acc = __half2float(g_h2s[(size_t)n * OUT2 + lane]);  // self term
    int roff = g_roffb[n];      // 16B-aligned
    int deg  = g_degb[n];
    int j = 0;
    for (; j + 8 <= deg; j += 8) {
        int4 sa = *(const int4*)&g_csrb[roff + j];
        int4 sb = *(const int4*)&g_csrb[roff + j + 4];
        float v0 = __half2float(g_h2s[(size_t)sa.x * OUT2 + lane]);
        float v1 = __half2float(g_h2s[(size_t)sa.y * OUT2 + lane]);
        float v2 = __half2float(g_h2s[(size_t)sa.z * OUT2 + lane]);
        float v3 = __half2float(g_h2s[(size_t)sa.w * OUT2 + lane]);
        float v4 = __half2float(g_h2s[(size_t)sb.x * OUT2 + lane]);
        float v5 = __half2float(g_h2s[(size_t)sb.y * OUT2 + lane]);
        float v6 = __half2float(g_h2s[(size_t)sb.z * OUT2 + lane]);
        float v7 = __half2float(g_h2s[(size_t)sb.w * OUT2 + lane]);
        acc += ((v0 + v1) + (v2 + v3)) + ((v4 + v5) + (v6 + v7));
    }
    for (; j + 4 <= deg; j += 4) {
        int4 sa = *(const int4*)&g_csrb[roff + j];
        acc += __half2float(g_h2s[(size_t)sa.x * OUT2 + lane])
             + __half2float(g_h2s[(size_t)sa.y * OUT2 + lane])
             + __half2float(g_h2s[(size_t)sa.z * OUT2 + lane])
             + __half2float(g_h2s[(size_t)sa.w * OUT2 + lane]);
    }
    if (j < deg) {
        int4 sa = *(const int4*)&g_csrb[roff + j];   // padded slot: safe
        int rem = deg - j;
        int sv[3] = {sa.x, sa.y, sa.z};
        for (int q = 0; q < 3; q++)
            if (q < rem)
                acc += __half2float(g_h2s[(size_t)sv[q] * OUT2 + lane]);
    }
    out[(size_t)n * OUT2 + lane] = b2[lane] + dv * acc;
}

// ---------------- launch (forked-stream graph; static resources) ----------------
extern "C" void kernel_launch(void* const* d_in, const int* in_sizes, int n_in,
                              void* d_out, int out_size) {
    const float* x       = (const float*)d_in[0];
    const float* W1      = (const float*)d_in[1];
    const float* att_src = (const float*)d_in[2];
    const float* att_dst = (const float*)d_in[3];
    const float* b1      = (const float*)d_in[4];
    const float* W2      = (const float*)d_in[5];
    const float* b2      = (const float*)d_in[6];
    const int* ei        = (const int*)d_in[7];
    const int* sei       = (const int*)d_in[8];
    float* out = (float*)d_out;

    int N = in_sizes[0] / C_IN;
    long long E  = in_sizes[7] / 2;
    long long E2 = in_sizes[8] / 2;
    int nb = (N + 255) / 256;

    int *p_dega, *p_degb, *p_roffa, *p_roffb, *p_cura, *p_curb;
    int *p_csra, *p_csrb, *p_bsa, *p_bsb, *p_fa, *p_fb;
    cudaGetSymbolAddress((void**)&p_dega, g_dega);
    cudaGetSymbolAddress((void**)&p_degb, g_degb);
    cudaGetSymbolAddress((void**)&p_roffa, g_roffa);
    cudaGetSymbolAddress((void**)&p_roffb, g_roffb);
    cudaGetSymbolAddress((void**)&p_cura, g_cura);
    cudaGetSymbolAddress((void**)&p_curb, g_curb);
    cudaGetSymbolAddress((void**)&p_csra, g_csra);
    cudaGetSymbolAddress((void**)&p_csrb, g_csrb);
    cudaGetSymbolAddress((void**)&p_bsa, g_bsa);
    cudaGetSymbolAddress((void**)&p_bsb, g_bsb);
    cudaGetSymbolAddress((void**)&p_fa, g_is64_a);
    cudaGetSymbolAddress((void**)&p_fb, g_is64_b);

    // created once on the correctness call; reused thereafter (no alloc in capture)
    static cudaStream_t s1 = nullptr, s2 = nullptr;
    static cudaEvent_t evF = nullptr, evA = nullptr, evB = nullptr;
    if (!s1) {
        cudaStreamCreateWithFlags(&s1, cudaStreamNonBlocking);
        cudaStreamCreateWithFlags(&s2, cudaStreamNonBlocking);
        cudaEventCreateWithFlags(&evF, cudaEventDisableTiming);
        cudaEventCreateWithFlags(&evA, cudaEventDisableTiming);
        cudaEventCreateWithFlags(&evB, cudaEventDisableTiming);
    }

    // detect on origin stream first (both CSR branches need the dtype flags)
    k_detect<<<1, 128>>>(ei, sei);
    cudaEventRecord(evF, 0);
    cudaStreamWaitEvent(s1, evF, 0);
    cudaStreamWaitEvent(s2, evF, 0);

    // branch S1: GAT CSR
    k_zero<<<nb, 256, 0, s1>>>(p_dega, N);
    k_hist<<<(unsigned)((E + 255) / 256), 256, 0, s1>>>(ei, E, p_dega, p_fa);
    k_bsum<<<nb, 256, 0, s1>>>(p_dega, N, p_bsa);
    k_topscan<<<1, 512, 0, s1>>>(p_bsa, nb);
    k_rowoff<<<nb, 256, 0, s1>>>(p_dega, p_bsa, p_roffa, p_cura, N);
    k_scatter<<<(unsigned)((E + 255) / 256), 256, 0, s1>>>(ei, E, p_fa, p_cura, p_csra);
    cudaEventRecord(evA, s1);

    // branch S2: GCN CSR
    k_zero<<<nb, 256, 0, s2>>>(p_degb, N);
    k_hist<<<(unsigned)((E2 + 255) / 256), 256, 0, s2>>>(sei, E2, p_degb, p_fb);
    k_bsum<<<nb, 256, 0, s2>>>(p_degb, N, p_bsb);
    k_topscan<<<1, 512, 0, s2>>>(p_bsb, nb);
    k_rowoff<<<nb, 256, 0, s2>>>(p_degb, p_bsb, p_roffb, p_curb, N);
    k_scatter<<<(unsigned)((E2 + 255) / 256), 256, 0, s2>>>(sei, E2, p_fb, p_curb, p_csrb);
    cudaEventRecord(evB, s2);

    // origin stream: dense compute with fused attention
    k_gemm1<<<(N + 63) / 64, 256>>>(x, W1, att_src, att_dst, N);

    cudaStreamWaitEvent(0, evA, 0);
    k_gat_gather<<<(N * 32 + 255) / 256, 256>>>(b1, N);
    cudaStreamWaitEvent(0, evB, 0);
    k_gcn_prep<<<(N + 7) / 8, 256>>>(W2, N);
    k_gcn_gather<<<(N * 32 + 255) / 256, 256>>>(b2, out, N);
}